// round 1
// baseline (speedup 1.0000x reference)
#include <cuda_runtime.h>
#include <cstdint>

// ---------------------------------------------------------------------------
// LSTMRegressor: 2-layer LSTM (B=256,T=512,D=64,H=512) + FC(512)+ReLU + FC(8)
// Persistent-kernel design: 128 CTAs, one grid barrier per time tick.
// CTA b owns hidden columns [4b, 4b+4) of BOTH layers (layer1 lags 1 tick).
// ---------------------------------------------------------------------------

#define NB      128
#define THREADS 256
#define HPAD    68              // 64 + 4 pad (floats) -> conflict-free float4 LDS
#define HBUF    (256 * HPAD)    // one h-chunk buffer  (256 rows x 64 cols)
#define WBUF    (16 * 64)       // one w-chunk buffer  (16 gate cols x 64 k)
#define SMEM_FLOATS (2 * HBUF + 2 * WBUF)
#define SMEM_BYTES  (SMEM_FLOATS * 4)

// Persistent device state (scratch; allocation-free per harness rules)
__device__ float g_h0[2][256 * 512];
__device__ float g_h1[2][256 * 512];
__device__ unsigned g_bar_count;
__device__ unsigned g_bar_gen;

// ---------------------------------------------------------------------------
// helpers
// ---------------------------------------------------------------------------
__device__ __forceinline__ void cp16(float* sdst, const float* gsrc) {
    unsigned a = (unsigned)__cvta_generic_to_shared(sdst);
    asm volatile("cp.async.cg.shared.global [%0], [%1], 16;" :: "r"(a), "l"(gsrc));
}
__device__ __forceinline__ void cp_commit() { asm volatile("cp.async.commit_group;"); }
__device__ __forceinline__ void cp_wait0()  { asm volatile("cp.async.wait_group 0;"); }
__device__ __forceinline__ void cp_wait1()  { asm volatile("cp.async.wait_group 1;"); }

__device__ __forceinline__ float sigf(float x) {
    return __fdividef(1.0f, 1.0f + __expf(-x));
}
__device__ __forceinline__ float tanhfast(float x) {
    // 1 - 2/(e^{2x}+1); handles +/-inf saturation correctly
    return 1.0f - __fdividef(2.0f, __expf(2.0f * x) + 1.0f);
}

__device__ __forceinline__ void grid_barrier() {
    __threadfence();            // make this CTA's h-writes globally visible
    __syncthreads();
    if (threadIdx.x == 0) {
        unsigned gen = *((volatile unsigned*)&g_bar_gen);
        unsigned arrived = atomicAdd(&g_bar_count, 1u);
        if (arrived == NB - 1) {
            g_bar_count = 0;
            __threadfence();
            atomicAdd(&g_bar_gen, 1u);   // release
        } else {
            while (*((volatile unsigned*)&g_bar_gen) == gen) { __nanosleep(128); }
        }
    }
    __syncthreads();
}

// Issue async load of one 64-wide K chunk: h-block [256][64] + w-block [16][64]
__device__ __forceinline__ void issue_chunk(
    float* shh, float* shw,
    const float* __restrict__ src, long srcStride, int col0,
    const float* __restrict__ W, int Wld, int k0, int cta)
{
    const int tid  = threadIdx.x;
    const int row0 = tid >> 4;
    const int k4   = tid & 15;
    const float* s0 = src + col0 + k0 + (k4 << 2);
    float* d0 = shh + (k4 << 2);
    #pragma unroll
    for (int ii = 0; ii < 16; ++ii) {
        int row = row0 + (ii << 4);
        cp16(d0 + row * HPAD, s0 + (long)row * srcStride);
    }
    // weights: thread t loads gate-row (t>>4), float4 (t&15)
    {
        int c  = tid >> 4;
        int gc = ((c >> 2) << 9) + (cta << 2) + (c & 3);   // gate column in [0,2048)
        cp16(shw + c * 64 + (k4 << 2), W + (long)gc * Wld + k0 + (k4 << 2));
    }
    cp_commit();
}

__device__ __forceinline__ void compute_chunk(
    float acc[16], const float* shh, const float* shw, int r)
{
    #pragma unroll 2
    for (int k = 0; k < 64; k += 4) {
        float4 a = *(const float4*)&shh[r * HPAD + k];
        #pragma unroll
        for (int c = 0; c < 16; ++c) {
            float4 w = *(const float4*)&shw[c * 64 + k];
            acc[c] = fmaf(a.x, w.x, acc[c]);
            acc[c] = fmaf(a.y, w.y, acc[c]);
            acc[c] = fmaf(a.z, w.z, acc[c]);
            acc[c] = fmaf(a.w, w.w, acc[c]);
        }
    }
}

// acc[c] += sum_k src[row][col0+k] * W[gatecol(c)][k],  k in [0, ncols)
__device__ __forceinline__ void accum_part(
    float acc[16],
    const float* __restrict__ src, long srcStride, int col0, int ncols,
    const float* __restrict__ W, int Wld, int cta, int r,
    float* shh, float* shw)
{
    const int nchunk = ncols >> 6;
    issue_chunk(shh, shw, src, srcStride, col0, W, Wld, 0, cta);
    for (int ci = 0; ci < nchunk; ++ci) {
        float* curh = shh + (ci & 1) * HBUF;
        float* curw = shw + (ci & 1) * WBUF;
        if (ci + 1 < nchunk) {
            issue_chunk(shh + ((ci + 1) & 1) * HBUF, shw + ((ci + 1) & 1) * WBUF,
                        src, srcStride, col0, W, Wld, (ci + 1) << 6, cta);
            cp_wait1();
        } else {
            cp_wait0();
        }
        __syncthreads();
        compute_chunk(acc, curh, curw, r);
        __syncthreads();
    }
}

__device__ __forceinline__ void cell_update(
    const float acc[16], const float bias[16], float cst[4],
    float* __restrict__ hout, int r, int cta)
{
    #pragma unroll
    for (int j = 0; j < 4; ++j) {
        float ig = sigf(acc[j]        + bias[j]);
        float fg = sigf(acc[4 + j]    + bias[4 + j]);
        float gg = tanhfast(acc[8 + j]  + bias[8 + j]);
        float og = sigf(acc[12 + j]   + bias[12 + j]);
        float cc = fmaf(fg, cst[j], ig * gg);
        cst[j] = cc;
        float h = og * tanhfast(cc);
        __stcg(hout + r * 512 + (cta << 2) + j, h);
    }
}

// ---------------------------------------------------------------------------
// main persistent kernel
// ---------------------------------------------------------------------------
__global__ void __launch_bounds__(THREADS, 1) lstm_kernel(
    const float* __restrict__ x,
    const float* __restrict__ Wih0, const float* __restrict__ Whh0,
    const float* __restrict__ bi0,  const float* __restrict__ bh0,
    const float* __restrict__ Wih1, const float* __restrict__ Whh1,
    const float* __restrict__ bi1,  const float* __restrict__ bh1,
    const float* __restrict__ Wfc1, const float* __restrict__ bfc1,
    const float* __restrict__ Wfc2, const float* __restrict__ bfc2,
    float* __restrict__ out)
{
    extern __shared__ float smem[];
    float* shh = smem;                 // 2 * HBUF
    float* shw = smem + 2 * HBUF;      // 2 * WBUF

    const int r   = threadIdx.x;       // batch row handled by this thread
    const int cta = blockIdx.x;        // hidden-column group [4*cta, 4*cta+4)

    // hoist biases (b_ih + b_hh) for both layers into registers
    float bias0[16], bias1[16];
    #pragma unroll
    for (int c = 0; c < 16; ++c) {
        int gc = ((c >> 2) << 9) + (cta << 2) + (c & 3);
        bias0[c] = bi0[gc] + bh0[gc];
        bias1[c] = bi1[gc] + bh1[gc];
    }

    float c0[4] = {0.f, 0.f, 0.f, 0.f};
    float c1[4] = {0.f, 0.f, 0.f, 0.f};

    // tick t: layer0 processes step t (t<512); layer1 processes step t-1 (t>=1)
    for (int t = 0; t <= 512; ++t) {
        if (t < 512) {
            float acc[16];
            #pragma unroll
            for (int c = 0; c < 16; ++c) acc[c] = 0.f;
            // x contribution: x[b][t][0:64]
            accum_part(acc, x, (long)512 * 64, t * 64, 64, Wih0, 64, cta, r, shh, shw);
            // recurrent contribution
            if (t > 0)
                accum_part(acc, g_h0[(t - 1) & 1], 512, 0, 512, Whh0, 512, cta, r, shh, shw);
            cell_update(acc, bias0, c0, g_h0[t & 1], r, cta);
        }
        if (t >= 1) {
            const int s = t - 1;
            float acc[16];
            #pragma unroll
            for (int c = 0; c < 16; ++c) acc[c] = 0.f;
            // input contribution from layer0 output at step s
            accum_part(acc, g_h0[s & 1], 512, 0, 512, Wih1, 512, cta, r, shh, shw);
            // recurrent contribution
            if (s > 0)
                accum_part(acc, g_h1[(s - 1) & 1], 512, 0, 512, Whh1, 512, cta, r, shh, shw);
            cell_update(acc, bias1, c1, g_h1[s & 1], r, cta);
        }
        grid_barrier();
    }

    // -----------------------------------------------------------------------
    // FC head: rows [2*cta, 2*cta+2) of h1[:, 511, :]  (parity 511&1 == 1)
    // -----------------------------------------------------------------------
    const float* hlast = g_h1[1];
    const int r0 = 2 * cta;
    float* shA = smem;            // [2][512] last hidden rows
    float* shZ = smem + 1024;     // [2][512] relu(fc1)

    for (int i = threadIdx.x; i < 1024; i += THREADS) {
        int row = i >> 9, k = i & 511;
        shA[i] = __ldcg(hlast + (long)(r0 + row) * 512 + k);
    }
    __syncthreads();

    #pragma unroll
    for (int ii = 0; ii < 2; ++ii) {
        int cc = threadIdx.x + THREADS * ii;      // fc1 output column
        float a0 = bfc1[cc];
        float a1 = a0;
        const float4* wr  = (const float4*)(Wfc1 + (long)cc * 512);
        const float4* hv0 = (const float4*)shA;
        const float4* hv1 = (const float4*)(shA + 512);
        #pragma unroll 4
        for (int k4 = 0; k4 < 128; ++k4) {
            float4 w = wr[k4];
            float4 p = hv0[k4];
            float4 q = hv1[k4];
            a0 = fmaf(w.x, p.x, a0); a0 = fmaf(w.y, p.y, a0);
            a0 = fmaf(w.z, p.z, a0); a0 = fmaf(w.w, p.w, a0);
            a1 = fmaf(w.x, q.x, a1); a1 = fmaf(w.y, q.y, a1);
            a1 = fmaf(w.z, q.z, a1); a1 = fmaf(w.w, q.w, a1);
        }
        shZ[cc]       = fmaxf(a0, 0.f);
        shZ[512 + cc] = fmaxf(a1, 0.f);
    }
    __syncthreads();

    // fc2: 8 warps, warp w computes output column w for both rows
    const int wpid = threadIdx.x >> 5;
    const int lane = threadIdx.x & 31;
    #pragma unroll
    for (int row = 0; row < 2; ++row) {
        const float4* zz = (const float4*)(shZ + row * 512);
        const float4* wf = (const float4*)(Wfc2 + (long)wpid * 512);
        float s = 0.f;
        #pragma unroll
        for (int k4 = lane; k4 < 128; k4 += 32) {
            float4 ww = wf[k4];
            float4 zv = zz[k4];
            s = fmaf(ww.x, zv.x, s); s = fmaf(ww.y, zv.y, s);
            s = fmaf(ww.z, zv.z, s); s = fmaf(ww.w, zv.w, s);
        }
        #pragma unroll
        for (int off = 16; off; off >>= 1) s += __shfl_xor_sync(0xFFFFFFFFu, s, off);
        if (lane == 0) out[(r0 + row) * 8 + wpid] = s + bfc2[wpid];
    }
}

// ---------------------------------------------------------------------------
// launch
// ---------------------------------------------------------------------------
extern "C" void kernel_launch(void* const* d_in, const int* in_sizes, int n_in,
                              void* d_out, int out_size)
{
    const float* x    = (const float*)d_in[0];
    const float* Wih0 = (const float*)d_in[1];
    const float* Whh0 = (const float*)d_in[2];
    const float* bi0  = (const float*)d_in[3];
    const float* bh0  = (const float*)d_in[4];
    const float* Wih1 = (const float*)d_in[5];
    const float* Whh1 = (const float*)d_in[6];
    const float* bi1  = (const float*)d_in[7];
    const float* bh1  = (const float*)d_in[8];
    const float* Wfc1 = (const float*)d_in[9];
    const float* bfc1 = (const float*)d_in[10];
    const float* Wfc2 = (const float*)d_in[11];
    const float* bfc2 = (const float*)d_in[12];
    float* out = (float*)d_out;

    cudaFuncSetAttribute(lstm_kernel, cudaFuncAttributeMaxDynamicSharedMemorySize,
                         SMEM_BYTES);

    lstm_kernel<<<NB, THREADS, SMEM_BYTES>>>(
        x, Wih0, Whh0, bi0, bh0, Wih1, Whh1, bi1, bh1,
        Wfc1, bfc1, Wfc2, bfc2, out);
}

// round 2
// speedup vs baseline: 1.0012x; 1.0012x over previous
#include <cuda_runtime.h>
#include <cstdint>

// ---------------------------------------------------------------------------
// LSTMRegressor: 2-layer LSTM (B=256,T=512,D=64,H=512) + FC(512)+ReLU + FC(8)
// Persistent-kernel design: 128 CTAs, one grid barrier per time tick.
// CTA b owns hidden columns [4b, 4b+4) of BOTH layers (layer1 lags 1 tick).
// ---------------------------------------------------------------------------

#define NB      128
#define THREADS 256
#define HPAD    68              // 64 + 4 pad (floats) -> conflict-free float4 LDS
#define HBUF    (256 * HPAD)    // one h-chunk buffer  (256 rows x 64 cols)
#define WBUF    (16 * 64)       // one w-chunk buffer  (16 gate cols x 64 k)
#define SMEM_FLOATS (2 * HBUF + 2 * WBUF)
#define SMEM_BYTES  (SMEM_FLOATS * 4)

// Persistent device state (scratch; allocation-free per harness rules)
__device__ float g_h0[2][256 * 512];
__device__ float g_h1[2][256 * 512];
__device__ unsigned g_bar_count;
__device__ unsigned g_bar_gen;

// ---------------------------------------------------------------------------
// helpers
// ---------------------------------------------------------------------------
__device__ __forceinline__ void cp16(float* sdst, const float* gsrc) {
    unsigned a = (unsigned)__cvta_generic_to_shared(sdst);
    asm volatile("cp.async.cg.shared.global [%0], [%1], 16;" :: "r"(a), "l"(gsrc));
}
__device__ __forceinline__ void cp_commit() { asm volatile("cp.async.commit_group;"); }
__device__ __forceinline__ void cp_wait0()  { asm volatile("cp.async.wait_group 0;"); }
__device__ __forceinline__ void cp_wait1()  { asm volatile("cp.async.wait_group 1;"); }

__device__ __forceinline__ float sigf(float x) {
    return __fdividef(1.0f, 1.0f + __expf(-x));
}
__device__ __forceinline__ float tanhfast(float x) {
    // 1 - 2/(e^{2x}+1); handles +/-inf saturation correctly
    return 1.0f - __fdividef(2.0f, __expf(2.0f * x) + 1.0f);
}

__device__ __forceinline__ void grid_barrier() {
    __threadfence();            // make this CTA's h-writes globally visible
    __syncthreads();
    if (threadIdx.x == 0) {
        unsigned gen = *((volatile unsigned*)&g_bar_gen);
        unsigned arrived = atomicAdd(&g_bar_count, 1u);
        if (arrived == NB - 1) {
            g_bar_count = 0;
            __threadfence();
            atomicAdd(&g_bar_gen, 1u);   // release
        } else {
            while (*((volatile unsigned*)&g_bar_gen) == gen) { __nanosleep(128); }
        }
    }
    __syncthreads();
}

// Issue async load of one 64-wide K chunk: h-block [256][64] + w-block [16][64]
__device__ __forceinline__ void issue_chunk(
    float* shh, float* shw,
    const float* __restrict__ src, long srcStride, int col0,
    const float* __restrict__ W, int Wld, int k0, int cta)
{
    const int tid  = threadIdx.x;
    const int row0 = tid >> 4;
    const int k4   = tid & 15;
    const float* s0 = src + col0 + k0 + (k4 << 2);
    float* d0 = shh + (k4 << 2);
    #pragma unroll
    for (int ii = 0; ii < 16; ++ii) {
        int row = row0 + (ii << 4);
        cp16(d0 + row * HPAD, s0 + (long)row * srcStride);
    }
    // weights: thread t loads gate-row (t>>4), float4 (t&15)
    {
        int c  = tid >> 4;
        int gc = ((c >> 2) << 9) + (cta << 2) + (c & 3);   // gate column in [0,2048)
        cp16(shw + c * 64 + (k4 << 2), W + (long)gc * Wld + k0 + (k4 << 2));
    }
    cp_commit();
}

__device__ __forceinline__ void compute_chunk(
    float acc[16], const float* shh, const float* shw, int r)
{
    #pragma unroll 2
    for (int k = 0; k < 64; k += 4) {
        float4 a = *(const float4*)&shh[r * HPAD + k];
        #pragma unroll
        for (int c = 0; c < 16; ++c) {
            float4 w = *(const float4*)&shw[c * 64 + k];
            acc[c] = fmaf(a.x, w.x, acc[c]);
            acc[c] = fmaf(a.y, w.y, acc[c]);
            acc[c] = fmaf(a.z, w.z, acc[c]);
            acc[c] = fmaf(a.w, w.w, acc[c]);
        }
    }
}

// acc[c] += sum_k src[row][col0+k] * W[gatecol(c)][k],  k in [0, ncols)
__device__ __forceinline__ void accum_part(
    float acc[16],
    const float* __restrict__ src, long srcStride, int col0, int ncols,
    const float* __restrict__ W, int Wld, int cta, int r,
    float* shh, float* shw)
{
    const int nchunk = ncols >> 6;
    issue_chunk(shh, shw, src, srcStride, col0, W, Wld, 0, cta);
    for (int ci = 0; ci < nchunk; ++ci) {
        float* curh = shh + (ci & 1) * HBUF;
        float* curw = shw + (ci & 1) * WBUF;
        if (ci + 1 < nchunk) {
            issue_chunk(shh + ((ci + 1) & 1) * HBUF, shw + ((ci + 1) & 1) * WBUF,
                        src, srcStride, col0, W, Wld, (ci + 1) << 6, cta);
            cp_wait1();
        } else {
            cp_wait0();
        }
        __syncthreads();
        compute_chunk(acc, curh, curw, r);
        __syncthreads();
    }
}

__device__ __forceinline__ void cell_update(
    const float acc[16], const float bias[16], float cst[4],
    float* __restrict__ hout, int r, int cta)
{
    #pragma unroll
    for (int j = 0; j < 4; ++j) {
        float ig = sigf(acc[j]        + bias[j]);
        float fg = sigf(acc[4 + j]    + bias[4 + j]);
        float gg = tanhfast(acc[8 + j]  + bias[8 + j]);
        float og = sigf(acc[12 + j]   + bias[12 + j]);
        float cc = fmaf(fg, cst[j], ig * gg);
        cst[j] = cc;
        float h = og * tanhfast(cc);
        __stcg(hout + r * 512 + (cta << 2) + j, h);
    }
}

// ---------------------------------------------------------------------------
// main persistent kernel
// ---------------------------------------------------------------------------
__global__ void __launch_bounds__(THREADS, 1) lstm_kernel(
    const float* __restrict__ x,
    const float* __restrict__ Wih0, const float* __restrict__ Whh0,
    const float* __restrict__ bi0,  const float* __restrict__ bh0,
    const float* __restrict__ Wih1, const float* __restrict__ Whh1,
    const float* __restrict__ bi1,  const float* __restrict__ bh1,
    const float* __restrict__ Wfc1, const float* __restrict__ bfc1,
    const float* __restrict__ Wfc2, const float* __restrict__ bfc2,
    float* __restrict__ out)
{
    extern __shared__ float smem[];
    float* shh = smem;                 // 2 * HBUF
    float* shw = smem + 2 * HBUF;      // 2 * WBUF

    const int r   = threadIdx.x;       // batch row handled by this thread
    const int cta = blockIdx.x;        // hidden-column group [4*cta, 4*cta+4)

    // hoist biases (b_ih + b_hh) for both layers into registers
    float bias0[16], bias1[16];
    #pragma unroll
    for (int c = 0; c < 16; ++c) {
        int gc = ((c >> 2) << 9) + (cta << 2) + (c & 3);
        bias0[c] = bi0[gc] + bh0[gc];
        bias1[c] = bi1[gc] + bh1[gc];
    }

    float c0[4] = {0.f, 0.f, 0.f, 0.f};
    float c1[4] = {0.f, 0.f, 0.f, 0.f};

    // tick t: layer0 processes step t (t<512); layer1 processes step t-1 (t>=1)
    for (int t = 0; t <= 512; ++t) {
        if (t < 512) {
            float acc[16];
            #pragma unroll
            for (int c = 0; c < 16; ++c) acc[c] = 0.f;
            // x contribution: x[b][t][0:64]
            accum_part(acc, x, (long)512 * 64, t * 64, 64, Wih0, 64, cta, r, shh, shw);
            // recurrent contribution
            if (t > 0)
                accum_part(acc, g_h0[(t - 1) & 1], 512, 0, 512, Whh0, 512, cta, r, shh, shw);
            cell_update(acc, bias0, c0, g_h0[t & 1], r, cta);
        }
        if (t >= 1) {
            const int s = t - 1;
            float acc[16];
            #pragma unroll
            for (int c = 0; c < 16; ++c) acc[c] = 0.f;
            // input contribution from layer0 output at step s
            accum_part(acc, g_h0[s & 1], 512, 0, 512, Wih1, 512, cta, r, shh, shw);
            // recurrent contribution
            if (s > 0)
                accum_part(acc, g_h1[(s - 1) & 1], 512, 0, 512, Whh1, 512, cta, r, shh, shw);
            cell_update(acc, bias1, c1, g_h1[s & 1], r, cta);
        }
        grid_barrier();
    }

    // -----------------------------------------------------------------------
    // FC head: rows [2*cta, 2*cta+2) of h1[:, 511, :]  (parity 511&1 == 1)
    // -----------------------------------------------------------------------
    const float* hlast = g_h1[1];
    const int r0 = 2 * cta;
    float* shA = smem;            // [2][512] last hidden rows
    float* shZ = smem + 1024;     // [2][512] relu(fc1)

    for (int i = threadIdx.x; i < 1024; i += THREADS) {
        int row = i >> 9, k = i & 511;
        shA[i] = __ldcg(hlast + (long)(r0 + row) * 512 + k);
    }
    __syncthreads();

    #pragma unroll
    for (int ii = 0; ii < 2; ++ii) {
        int cc = threadIdx.x + THREADS * ii;      // fc1 output column
        float a0 = bfc1[cc];
        float a1 = a0;
        const float4* wr  = (const float4*)(Wfc1 + (long)cc * 512);
        const float4* hv0 = (const float4*)shA;
        const float4* hv1 = (const float4*)(shA + 512);
        #pragma unroll 4
        for (int k4 = 0; k4 < 128; ++k4) {
            float4 w = wr[k4];
            float4 p = hv0[k4];
            float4 q = hv1[k4];
            a0 = fmaf(w.x, p.x, a0); a0 = fmaf(w.y, p.y, a0);
            a0 = fmaf(w.z, p.z, a0); a0 = fmaf(w.w, p.w, a0);
            a1 = fmaf(w.x, q.x, a1); a1 = fmaf(w.y, q.y, a1);
            a1 = fmaf(w.z, q.z, a1); a1 = fmaf(w.w, q.w, a1);
        }
        shZ[cc]       = fmaxf(a0, 0.f);
        shZ[512 + cc] = fmaxf(a1, 0.f);
    }
    __syncthreads();

    // fc2: 8 warps, warp w computes output column w for both rows
    const int wpid = threadIdx.x >> 5;
    const int lane = threadIdx.x & 31;
    #pragma unroll
    for (int row = 0; row < 2; ++row) {
        const float4* zz = (const float4*)(shZ + row * 512);
        const float4* wf = (const float4*)(Wfc2 + (long)wpid * 512);
        float s = 0.f;
        #pragma unroll
        for (int k4 = lane; k4 < 128; k4 += 32) {
            float4 ww = wf[k4];
            float4 zv = zz[k4];
            s = fmaf(ww.x, zv.x, s); s = fmaf(ww.y, zv.y, s);
            s = fmaf(ww.z, zv.z, s); s = fmaf(ww.w, zv.w, s);
        }
        #pragma unroll
        for (int off = 16; off; off >>= 1) s += __shfl_xor_sync(0xFFFFFFFFu, s, off);
        if (lane == 0) out[(r0 + row) * 8 + wpid] = s + bfc2[wpid];
    }
}

// ---------------------------------------------------------------------------
// launch
// ---------------------------------------------------------------------------
extern "C" void kernel_launch(void* const* d_in, const int* in_sizes, int n_in,
                              void* d_out, int out_size)
{
    const float* x    = (const float*)d_in[0];
    const float* Wih0 = (const float*)d_in[1];
    const float* Whh0 = (const float*)d_in[2];
    const float* bi0  = (const float*)d_in[3];
    const float* bh0  = (const float*)d_in[4];
    const float* Wih1 = (const float*)d_in[5];
    const float* Whh1 = (const float*)d_in[6];
    const float* bi1  = (const float*)d_in[7];
    const float* bh1  = (const float*)d_in[8];
    const float* Wfc1 = (const float*)d_in[9];
    const float* bfc1 = (const float*)d_in[10];
    const float* Wfc2 = (const float*)d_in[11];
    const float* bfc2 = (const float*)d_in[12];
    float* out = (float*)d_out;

    cudaFuncSetAttribute(lstm_kernel, cudaFuncAttributeMaxDynamicSharedMemorySize,
                         SMEM_BYTES);

    lstm_kernel<<<NB, THREADS, SMEM_BYTES>>>(
        x, Wih0, Whh0, bi0, bh0, Wih1, Whh1, bi1, bh1,
        Wfc1, bfc1, Wfc2, bfc2, out);
}